// round 3
// baseline (speedup 1.0000x reference)
#include <cuda_runtime.h>
#include <cuda_bf16.h>

// Problem constants (fixed by the reference: B=2048, C=16, H=32, W=32 -> F=16384)
#define B_SAMPLES 2048
#define F_FEATS   16384
#define THREADS   128
#define NBLOCKS   (B_SAMPLES * 2)   // half-row per CTA

// Scratch (no device allocation allowed): per-half-row {ssq, cnt} partials,
// stored as float4 per row = {ssq0, cnt0, ssq1, cnt1} for 1-LDG.128 readback.
__device__ float4       g_part4[B_SAMPLES];
__device__ unsigned int g_arrive_count = 0;   // reset by the last block each run

__global__ __launch_bounds__(THREADS, 16)
void fnmse_fused_kernel(const float* __restrict__ out,
                        const float* __restrict__ tgt,
                        const float* __restrict__ fw,
                        float* __restrict__ d_out)
{
    const int bid  = blockIdx.x;
    const int b    = bid >> 1;       // sample row
    const int half = bid & 1;        // which half of the row
    const int tid  = threadIdx.x;

    const size_t base = (size_t)b * F_FEATS + (size_t)half * (F_FEATS / 2);
    const float4* __restrict__ o4 = reinterpret_cast<const float4*>(out + base);
    const float4* __restrict__ t4 = reinterpret_cast<const float4*>(tgt + base);
    const float4* __restrict__ w4 = reinterpret_cast<const float4*>(fw + (size_t)half * (F_FEATS / 2));

    float ssq = 0.0f;
    float cnt = 0.0f;

    // Half-row = 8192 floats = 2048 float4; 128 threads -> 16 fully unrolled
    // iterations (deep MLP to hide DRAM latency). Streaming loads (.cs) for
    // the read-once tensors; fw stays L2/L1 resident.
#pragma unroll
    for (int it = 0; it < (F_FEATS / 8) / THREADS; ++it) {
        const int i = it * THREADS + tid;
        float4 o = __ldcs(&o4[i]);
        float4 t = __ldcs(&t4[i]);
        float4 w = __ldg(&w4[i]);

        {
            bool  m = (t.x == t.x);          // !isnan
            float r = m ? (t.x - o.x) : 0.0f;
            float s = r * w.x;
            ssq = fmaf(s, s, ssq);
            cnt += m ? 1.0f : 0.0f;
        }
        {
            bool  m = (t.y == t.y);
            float r = m ? (t.y - o.y) : 0.0f;
            float s = r * w.y;
            ssq = fmaf(s, s, ssq);
            cnt += m ? 1.0f : 0.0f;
        }
        {
            bool  m = (t.z == t.z);
            float r = m ? (t.z - o.z) : 0.0f;
            float s = r * w.z;
            ssq = fmaf(s, s, ssq);
            cnt += m ? 1.0f : 0.0f;
        }
        {
            bool  m = (t.w == t.w);
            float r = m ? (t.w - o.w) : 0.0f;
            float s = r * w.w;
            ssq = fmaf(s, s, ssq);
            cnt += m ? 1.0f : 0.0f;
        }
    }

    // Warp reduction
#pragma unroll
    for (int off = 16; off > 0; off >>= 1) {
        ssq += __shfl_down_sync(0xFFFFFFFFu, ssq, off);
        cnt += __shfl_down_sync(0xFFFFFFFFu, cnt, off);
    }

    __shared__ float s_ssq[THREADS / 32];
    __shared__ float s_cnt[THREADS / 32];
    const int lane = tid & 31;
    const int wid  = tid >> 5;
    if (lane == 0) { s_ssq[wid] = ssq; s_cnt[wid] = cnt; }
    __syncthreads();

    // Warps 1..3 are done: retire immediately (no trailing sync/fence for them).
    if (wid != 0) return;

    float vs = (lane < THREADS / 32) ? s_ssq[lane] : 0.0f;
    float vc = (lane < THREADS / 32) ? s_cnt[lane] : 0.0f;
#pragma unroll
    for (int off = 2; off > 0; off >>= 1) {
        vs += __shfl_down_sync(0xFFFFFFFFu, vs, off);
        vc += __shfl_down_sync(0xFFFFFFFFu, vc, off);
    }

    int is_last = 0;
    if (lane == 0) {
        // Deposit this half-row's partial, then release-arrive. The release
        // orders the STG.64 below before the counter increment; acq_rel gives
        // the winning (last) block acquire semantics for reading all partials.
        reinterpret_cast<float2*>(g_part4)[bid] = make_float2(vs, vc);
        unsigned int prev;
        asm volatile("atom.add.acq_rel.gpu.global.u32 %0, [%1], 1;"
                     : "=r"(prev) : "l"(&g_arrive_count) : "memory");
        is_last = (prev == (unsigned int)(NBLOCKS - 1));
    }
    is_last = __shfl_sync(0xFFFFFFFFu, is_last, 0);

    // Last-arriving block: warp 0 alone does the fixed-order deterministic
    // final combine (L2-resident 32KB, 64 LDG.128 per lane).
    if (is_last) {
        float s = 0.0f;
#pragma unroll 8
        for (int r = lane; r < B_SAMPLES; r += 32) {
            float4 a = g_part4[r];            // {ssq0, cnt0, ssq1, cnt1}
            s += (a.x + a.z) / (a.y + a.w);
        }
#pragma unroll
        for (int off = 16; off > 0; off >>= 1)
            s += __shfl_down_sync(0xFFFFFFFFu, s, off);
        if (lane == 0) {
            d_out[0] = s;
            g_arrive_count = 0u;   // reset for next graph replay
        }
    }
}

extern "C" void kernel_launch(void* const* d_in, const int* in_sizes, int n_in,
                              void* d_out, int out_size)
{
    // metadata order: output, target, e_exp, sample_weight, feature_weight
    const float* out = (const float*)d_in[0];
    const float* tgt = (const float*)d_in[1];
    // d_in[2] (e_exp) and d_in[3] (sample_weight) are unused by the reference.
    const float* fw  = (const float*)d_in[4];

    fnmse_fused_kernel<<<NBLOCKS, THREADS>>>(out, tgt, fw, (float*)d_out);
}

// round 4
// speedup vs baseline: 1.4544x; 1.4544x over previous
#include <cuda_runtime.h>
#include <cuda_bf16.h>

// Problem constants (fixed by the reference: B=2048, C=16, H=32, W=32 -> F=16384)
#define B_SAMPLES 2048
#define F_FEATS   16384
#define THREADS   256

// Scratch (no device allocation allowed).
__device__ float        g_per_sample[B_SAMPLES];
__device__ unsigned int g_arrive_count = 0;   // reset by the last block each run

__global__ __launch_bounds__(THREADS, 8)
void fnmse_fused_kernel(const float* __restrict__ out,
                        const float* __restrict__ tgt,
                        const float* __restrict__ fw,
                        float* __restrict__ d_out)
{
    const int b   = blockIdx.x;
    const int tid = threadIdx.x;

    const float4* __restrict__ o4 = reinterpret_cast<const float4*>(out + (size_t)b * F_FEATS);
    const float4* __restrict__ t4 = reinterpret_cast<const float4*>(tgt + (size_t)b * F_FEATS);
    const float4* __restrict__ w4 = reinterpret_cast<const float4*>(fw);

    float ssq = 0.0f;
    float cnt = 0.0f;

    // F/4 = 4096 float4 per row; 256 threads -> 16 iterations, fully unrolled
    // (deep MLP, plain LDG.128 — this exact loop measured 6.0+ TB/s in R1/R2;
    // do not add cache qualifiers or change CTA shape).
#pragma unroll
    for (int it = 0; it < (F_FEATS / 4) / THREADS; ++it) {
        const int i = it * THREADS + tid;
        float4 o = o4[i];
        float4 t = t4[i];
        float4 w = w4[i];

        {
            bool  m = (t.x == t.x);          // !isnan
            float r = m ? (t.x - o.x) : 0.0f;
            float s = r * w.x;
            ssq = fmaf(s, s, ssq);
            cnt += m ? 1.0f : 0.0f;
        }
        {
            bool  m = (t.y == t.y);
            float r = m ? (t.y - o.y) : 0.0f;
            float s = r * w.y;
            ssq = fmaf(s, s, ssq);
            cnt += m ? 1.0f : 0.0f;
        }
        {
            bool  m = (t.z == t.z);
            float r = m ? (t.z - o.z) : 0.0f;
            float s = r * w.z;
            ssq = fmaf(s, s, ssq);
            cnt += m ? 1.0f : 0.0f;
        }
        {
            bool  m = (t.w == t.w);
            float r = m ? (t.w - o.w) : 0.0f;
            float s = r * w.w;
            ssq = fmaf(s, s, ssq);
            cnt += m ? 1.0f : 0.0f;
        }
    }

    // Warp reduction
#pragma unroll
    for (int off = 16; off > 0; off >>= 1) {
        ssq += __shfl_down_sync(0xFFFFFFFFu, ssq, off);
        cnt += __shfl_down_sync(0xFFFFFFFFu, cnt, off);
    }

    __shared__ float s_ssq[THREADS / 32];
    __shared__ float s_cnt[THREADS / 32];
    const int lane = tid & 31;
    const int wid  = tid >> 5;
    if (lane == 0) { s_ssq[wid] = ssq; s_cnt[wid] = cnt; }
    __syncthreads();

    // Warps 1..7 retire immediately — no fence, no trailing barrier.
    if (wid != 0) return;

    float vs = (lane < THREADS / 32) ? s_ssq[lane] : 0.0f;
    float vc = (lane < THREADS / 32) ? s_cnt[lane] : 0.0f;
#pragma unroll
    for (int off = 4; off > 0; off >>= 1) {
        vs += __shfl_down_sync(0xFFFFFFFFu, vs, off);
        vc += __shfl_down_sync(0xFFFFFFFFu, vc, off);
    }

    int is_last = 0;
    if (lane == 0) {
        // Deposit the per-sample value, then release-arrive. The release on the
        // atomic orders the STG above it; acq_rel gives the last (winning)
        // block acquire semantics for reading all 2048 partials.
        g_per_sample[b] = vs / vc;
        unsigned int prev;
        asm volatile("atom.add.acq_rel.gpu.global.u32 %0, [%1], 1;"
                     : "=r"(prev) : "l"(&g_arrive_count) : "memory");
        is_last = (prev == (unsigned int)(gridDim.x - 1));
    }
    is_last = __shfl_sync(0xFFFFFFFFu, is_last, 0);

    // Last-arriving block: warp 0 alone does the fixed-order deterministic
    // final combine (8KB, L2-resident, 16 float4 loads per lane).
    if (is_last) {
        const float4* p4 = reinterpret_cast<const float4*>(g_per_sample);
        float s = 0.0f;
#pragma unroll
        for (int r = 0; r < B_SAMPLES / 4 / 32; ++r) {
            float4 a = p4[r * 32 + lane];
            s += (a.x + a.y) + (a.z + a.w);
        }
#pragma unroll
        for (int off = 16; off > 0; off >>= 1)
            s += __shfl_down_sync(0xFFFFFFFFu, s, off);
        if (lane == 0) {
            d_out[0] = s;
            g_arrive_count = 0u;   // reset for next graph replay
        }
    }
}

extern "C" void kernel_launch(void* const* d_in, const int* in_sizes, int n_in,
                              void* d_out, int out_size)
{
    // metadata order: output, target, e_exp, sample_weight, feature_weight
    const float* out = (const float*)d_in[0];
    const float* tgt = (const float*)d_in[1];
    // d_in[2] (e_exp) and d_in[3] (sample_weight) are unused by the reference.
    const float* fw  = (const float*)d_in[4];

    fnmse_fused_kernel<<<B_SAMPLES, THREADS>>>(out, tgt, fw, (float*)d_out);
}